// round 15
// baseline (speedup 1.0000x reference)
#include <cuda_runtime.h>
#include <cuda_fp16.h>
#include <cstdint>
#include <cstddef>

// ---------------------------------------------------------------------------
// word (8,2048,1024) f32, sent (8,512,1024) f32, W (1024,1024) f32
// out: combination (8,2048,2048) then g (8,2048,1024)
// mma.sync m16n8k16 fp16, 2-way split, 3-term (R13-proven arithmetic/layout).
// R15: B operands pre-rendered in global memory as the EXACT smem tile image
// (h0 tile + h1 tile, pitch 40 halves, per band x chunk) -> mainloop B load
// is pure cp.async. A keeps proven fp32+in-loop split, STS.128-packed.
// Both k16 steps' fragments are loaded up-front to kill dependency bubbles.
// ---------------------------------------------------------------------------

#define B_      8
#define S_      2048
#define NS_     512
#define E_      1024
#define M_TOT   (B_ * S_)

#define BM 128
#define BN 128
#define BK 32
#define NTHREADS 256

#define HP 40                            // halves per smem row (80 B pitch)
#define TILE_H (128 * HP)                // 5120 halves per tile
#define TILE_BYTES (TILE_H * 2)          // 10240
#define BLK_H (2 * TILE_H)               // h0+h1 image block = 10240 halves
#define BLK_BYTES (BLK_H * 2)            // 20480
#define STAGE_BYTES (4 * TILE_BYTES)     // A0 A1 B0 B1 = 40960
#define DYN_SMEM (2 * STAGE_BYTES)       // 81920

// ---- persistent scratch ----------------------------------------------------
__device__ float    g_scores[M_TOT * NS_];                 // 32 MB
__device__ unsigned short g_Wimg[8 * 32 * BLK_H];          // W image (1 batch)
__device__ unsigned short g_sentimg[B_ * 4 * 32 * BLK_H];  // sent image
__device__ unsigned short g_sentTimg[B_ * 8 * 16 * BLK_H]; // sent^T image

// ---------------------------------------------------------------------------
__device__ __forceinline__ uint32_t smem_u32(const void* p) {
    uint32_t a;
    asm("{ .reg .u64 t; cvta.to.shared.u64 t, %1; cvt.u32.u64 %0, t; }"
        : "=r"(a) : "l"(p));
    return a;
}

#define CP16(dst, src)                                                        \
    asm volatile("cp.async.cg.shared.global [%0], [%1], 16;"                  \
                 :: "r"(dst), "l"(src) : "memory")
#define CPCOMMIT() asm volatile("cp.async.commit_group;" ::: "memory")
#define CPWAIT0()  asm volatile("cp.async.wait_group 0;" ::: "memory")

#define LDMX4(r0, r1, r2, r3, addr)                                           \
    asm volatile("ldmatrix.sync.aligned.m8n8.x4.shared.b16 {%0,%1,%2,%3}, [%4];" \
                 : "=r"(r0), "=r"(r1), "=r"(r2), "=r"(r3) : "r"(addr))

__device__ __forceinline__ void mma16816(float* c, const uint32_t* a,
                                         const uint32_t* b) {
    asm volatile(
        "mma.sync.aligned.m16n8k16.row.col.f32.f16.f16.f32 "
        "{%0,%1,%2,%3}, {%4,%5,%6,%7}, {%8,%9}, {%0,%1,%2,%3};"
        : "+f"(c[0]), "+f"(c[1]), "+f"(c[2]), "+f"(c[3])
        : "r"(a[0]), "r"(a[1]), "r"(a[2]), "r"(a[3]), "r"(b[0]), "r"(b[1]));
}

// ---------------------------------------------------------------------------
// NT GEMM: C[m,n] = sum_k A[m,k]*B[n,k], 3-term fp16 split.
// Block 128x128 (warp 32x64, R13 layout), BK=32, double-buffered.
// A fp32 (in-loop split, STS.128); B via cp.async from pre-rendered image.
// ---------------------------------------------------------------------------
__global__ __launch_bounds__(NTHREADS, 1)
void gemm3i(const float* __restrict__ A, const unsigned short* __restrict__ Bimg,
            float* __restrict__ C, float* __restrict__ C2,
            int lda, int ldc, int ldc2, int K,
            size_t aB, size_t bB, size_t cB, size_t c2B)
{
    extern __shared__ char smc[];

    const int tid  = threadIdx.x;
    const int wid  = tid >> 5;
    const int lane = tid & 31;
    const int wm   = wid & 3;
    const int wn   = wid >> 2;
    const int lr   = lane >> 2;
    const int lc   = lane & 3;

    // A loader: 2 threads per row, 16 floats each
    const int lrow = tid >> 1;
    const int lkh  = (tid & 1) * 16;

    const float* Ag = A + (size_t)blockIdx.z * aB
                        + ((size_t)blockIdx.y * BM + lrow) * lda + lkh;

    const int NCH = K / BK;
    // B image: blocks of 20480 B per (band=blockIdx.x, chunk)
    const char* Bg = (const char*)(Bimg + (size_t)blockIdx.z * bB)
                   + ((size_t)blockIdx.x * NCH) * BLK_BYTES
                   + (size_t)tid * 80;

    const uint32_t offA = (uint32_t)(lrow * 80 + lkh * 2);   // bytes

    // ldmatrix per-lane addressing (R13-proven)
    const int msel = lane >> 3, mr = lane & 7;
    const int a_r = (msel & 1) * 8 + mr, a_c = (msel >> 1) * 8;
    const int b_r = (msel >> 1) * 8 + mr, b_c = (msel & 1) * 8;

    const uint32_t base_u = smem_u32(smc);
    uint32_t aAdr[2], bAdr[4];
#pragma unroll
    for (int i = 0; i < 2; i++)
        aAdr[i] = base_u + 2u * ((wm * 32 + i * 16 + a_r) * HP + a_c);
#pragma unroll
    for (int jp = 0; jp < 4; jp++)
        bAdr[jp] = base_u + 2u * TILE_BYTES
                 + 2u * ((wn * 64 + jp * 16 + b_r) * HP + b_c);

    const uint32_t bSm = base_u + 2u * TILE_BYTES + (uint32_t)tid * 80;

    float acc[2][8][4];
#pragma unroll
    for (int i = 0; i < 2; i++)
#pragma unroll
        for (int j = 0; j < 8; j++)
#pragma unroll
            for (int q = 0; q < 4; q++) acc[i][j][q] = 0.f;

    // A: split 16 fp32 -> h0/h1, 4x STS.128
#define STASH_A(stA_, sa)                                                      \
    do {                                                                       \
        uint32_t H0_[8], H1_[8];                                               \
        _Pragma("unroll")                                                      \
        for (int q = 0; q < 4; q++) {                                          \
            float4 a = (sa)[q];                                                \
            __half2 h0a = __floats2half2_rn(a.x, a.y);                         \
            __half2 h0b = __floats2half2_rn(a.z, a.w);                         \
            float2 ba = __half22float2(h0a), bb = __half22float2(h0b);         \
            __half2 h1a = __floats2half2_rn(a.x - ba.x, a.y - ba.y);           \
            __half2 h1b = __floats2half2_rn(a.z - bb.x, a.w - bb.y);           \
            H0_[2*q]   = *reinterpret_cast<uint32_t*>(&h0a);                   \
            H0_[2*q+1] = *reinterpret_cast<uint32_t*>(&h0b);                   \
            H1_[2*q]   = *reinterpret_cast<uint32_t*>(&h1a);                   \
            H1_[2*q+1] = *reinterpret_cast<uint32_t*>(&h1b);                   \
        }                                                                      \
        *(uint4*)((stA_) + offA)      = make_uint4(H0_[0], H0_[1], H0_[2], H0_[3]); \
        *(uint4*)((stA_) + offA + 16) = make_uint4(H0_[4], H0_[5], H0_[6], H0_[7]); \
        *(uint4*)((stA_) + TILE_BYTES + offA)      = make_uint4(H1_[0], H1_[1], H1_[2], H1_[3]); \
        *(uint4*)((stA_) + TILE_BYTES + offA + 16) = make_uint4(H1_[4], H1_[5], H1_[6], H1_[7]); \
    } while (0)

    // ---- prologue: stage 0 ------------------------------------------------
    {
#pragma unroll
        for (int q = 0; q < 5; q++)
            CP16(bSm + q * 16, Bg + q * 16);
        CPCOMMIT();
        float4 sa[4];
#pragma unroll
        for (int q = 0; q < 4; q++) sa[q] = *(const float4*)(Ag + 4 * q);
        STASH_A(smc, sa);
        CPWAIT0();
    }
    __syncthreads();

    // ---- main loop --------------------------------------------------------
    for (int c = 0; c < NCH; c++) {
        const int s = c & 1;
        const bool hasNext = (c + 1 < NCH);

        float4 sa[4];
        if (hasNext) {
            const uint32_t nb = bSm + (uint32_t)(s ^ 1) * STAGE_BYTES;
            const char*    ng = Bg + (size_t)(c + 1) * BLK_BYTES;
#pragma unroll
            for (int q = 0; q < 5; q++)
                CP16(nb + q * 16, ng + q * 16);
            CPCOMMIT();
            const float* ap = Ag + (size_t)(c + 1) * BK;
#pragma unroll
            for (int q = 0; q < 4; q++) sa[q] = *(const float4*)(ap + 4 * q);
        }

        const uint32_t so = (uint32_t)s * STAGE_BYTES;

        // load ALL fragments for both k16 steps up-front
        uint32_t a0[2][2][4], a1[2][2][4];
        uint32_t b0[2][8][2], b1[2][8][2];
#pragma unroll
        for (int ks = 0; ks < 2; ks++) {
            const uint32_t ko = so + ks * 32u;
#pragma unroll
            for (int i = 0; i < 2; i++) {
                LDMX4(a0[ks][i][0], a0[ks][i][1], a0[ks][i][2], a0[ks][i][3],
                      aAdr[i] + ko);
                LDMX4(a1[ks][i][0], a1[ks][i][1], a1[ks][i][2], a1[ks][i][3],
                      aAdr[i] + ko + TILE_BYTES);
            }
#pragma unroll
            for (int jp = 0; jp < 4; jp++) {
                LDMX4(b0[ks][2*jp][0], b0[ks][2*jp][1], b0[ks][2*jp+1][0],
                      b0[ks][2*jp+1][1], bAdr[jp] + ko);
                LDMX4(b1[ks][2*jp][0], b1[ks][2*jp][1], b1[ks][2*jp+1][0],
                      b1[ks][2*jp+1][1], bAdr[jp] + ko + TILE_BYTES);
            }
        }
#pragma unroll
        for (int ks = 0; ks < 2; ks++)
#pragma unroll
            for (int i = 0; i < 2; i++)
#pragma unroll
                for (int j = 0; j < 8; j++) {
                    mma16816(acc[i][j], a0[ks][i], b0[ks][j]);
                    mma16816(acc[i][j], a0[ks][i], b1[ks][j]);
                    mma16816(acc[i][j], a1[ks][i], b0[ks][j]);
                }

        if (hasNext)
            STASH_A(smc + (s ^ 1) * STAGE_BYTES, sa);
        CPWAIT0();
        __syncthreads();
    }
#undef STASH_A

    // ---- epilogue (R13 verbatim) ------------------------------------------
    float* Cb  = C + (size_t)blockIdx.z * cB + (size_t)blockIdx.x * BN;
    float* C2b = C2 ? C2 + (size_t)blockIdx.z * c2B + (size_t)blockIdx.x * BN
                    : nullptr;
#pragma unroll
    for (int i = 0; i < 2; i++) {
        const size_t mTop = (size_t)blockIdx.y * BM + wm * 32 + i * 16 + lr;
#pragma unroll
        for (int j = 0; j < 8; j++) {
            const int n0 = wn * 64 + j * 8 + 2 * lc;
            float2 v0 = make_float2(acc[i][j][0], acc[i][j][1]);
            float2 v1 = make_float2(acc[i][j][2], acc[i][j][3]);
            *(float2*)(Cb + mTop * ldc + n0)       = v0;
            *(float2*)(Cb + (mTop + 8) * ldc + n0) = v1;
            if (C2b) {
                *(float2*)(C2b + mTop * ldc2 + n0)       = v0;
                *(float2*)(C2b + (mTop + 8) * ldc2 + n0) = v1;
            }
        }
    }
}

// ---------------------------------------------------------------------------
// Build B tile image from a row-major [batch, rows, K] fp32 matrix.
// Image: per (batch, band=row/128, chunk=k/32): 20480-byte block =
//   h0 tile (128 x 40 halves) then h1 tile.
// ---------------------------------------------------------------------------
__global__ __launch_bounds__(256)
void build_img(const float* __restrict__ src, unsigned short* __restrict__ img,
               int rowsK2, int K2, int nch, int nbands, int n2)
{
    int i = blockIdx.x * 256 + threadIdx.x;
    if (i >= n2) return;
    int b   = i / rowsK2;
    int rem = i - b * rowsK2;
    int row = rem / K2;
    int k   = (rem - row * K2) * 2;

    float2 v = ((const float2*)src)[i];
    __half2 H = __floats2half2_rn(v.x, v.y);
    float2 r = __half22float2(H);
    __half2 L = __floats2half2_rn(v.x - r.x, v.y - r.y);

    size_t blk = (((size_t)b * nbands + (row >> 7)) * nch + (k >> 5)) * BLK_H;
    uint32_t off = (uint32_t)((row & 127) * HP + (k & 31));
    *(uint32_t*)(img + blk + off)          = *reinterpret_cast<uint32_t*>(&H);
    *(uint32_t*)(img + blk + off + TILE_H) = *reinterpret_cast<uint32_t*>(&L);
}

// ---------------------------------------------------------------------------
// Build sent^T tile image: element (row=e, k=n) = sent[b, n, e].
// ---------------------------------------------------------------------------
__global__ __launch_bounds__(256)
void build_imgT(const float* __restrict__ sent, unsigned short* __restrict__ img)
{
    __shared__ float t[32][33];
    const int b  = blockIdx.z;
    const int n0 = blockIdx.y * 32;
    const int e0 = blockIdx.x * 32;
    const int x = threadIdx.x, y = threadIdx.y;

    const float* src = sent + ((size_t)b * NS_ + n0) * E_ + e0;
#pragma unroll
    for (int k = 0; k < 4; k++)
        t[y + 8 * k][x] = src[(size_t)(y + 8 * k) * E_ + x];
    __syncthreads();
#pragma unroll
    for (int k = 0; k < 4; k++) {
        float v = t[x][y + 8 * k];
        __half h0 = __float2half_rn(v);
        __half h1 = __float2half_rn(v - __half2float(h0));
        const int e = e0 + y + 8 * k;
        const int n = n0 + x;
        size_t blk = (((size_t)b * 8 + (e >> 7)) * 16 + (n >> 5)) * BLK_H;
        uint32_t off = (uint32_t)((e & 127) * HP + (n & 31));
        img[blk + off]          = __half_as_ushort(h0);
        img[blk + off + TILE_H] = __half_as_ushort(h1);
    }
}

// ---------------------------------------------------------------------------
// In-place stable softmax over last dim (512) of g_scores.
// ---------------------------------------------------------------------------
__global__ __launch_bounds__(256)
void softmax_rows()
{
    __shared__ float redMax[8];
    __shared__ float redSum[8];

    float* row = g_scores + (size_t)blockIdx.x * NS_;
    const int t = threadIdx.x;

    float2 v = reinterpret_cast<float2*>(row)[t];

    float m = fmaxf(v.x, v.y);
#pragma unroll
    for (int o = 16; o > 0; o >>= 1)
        m = fmaxf(m, __shfl_xor_sync(0xffffffffu, m, o));
    if ((t & 31) == 0) redMax[t >> 5] = m;
    __syncthreads();
    float mAll = redMax[0];
#pragma unroll
    for (int i = 1; i < 8; i++) mAll = fmaxf(mAll, redMax[i]);

    float e0 = expf(v.x - mAll);
    float e1 = expf(v.y - mAll);
    float s = e0 + e1;
#pragma unroll
    for (int o = 16; o > 0; o >>= 1)
        s += __shfl_xor_sync(0xffffffffu, s, o);
    if ((t & 31) == 0) redSum[t >> 5] = s;
    __syncthreads();
    float sAll = 0.f;
#pragma unroll
    for (int i = 0; i < 8; i++) sAll += redSum[i];

    const float inv = 1.0f / sAll;
    reinterpret_cast<float2*>(row)[t] = make_float2(e0 * inv, e1 * inv);
}

// ---------------------------------------------------------------------------
extern "C" void kernel_launch(void* const* d_in, const int* in_sizes, int n_in,
                              void* d_out, int out_size)
{
    (void)out_size;
    const float* word = nullptr;
    const float* sent = nullptr;
    const float* W    = nullptr;
    for (int i = 0; i < n_in; i++) {
        if      (in_sizes[i] == M_TOT * E_)    word = (const float*)d_in[i];
        else if (in_sizes[i] == B_ * NS_ * E_) sent = (const float*)d_in[i];
        else if (in_sizes[i] == E_ * E_)       W    = (const float*)d_in[i];
    }

    float* out  = (float*)d_out;
    float* comb = out;                               // (8, 2048, 2048)
    float* gout = out + (size_t)M_TOT * 2 * E_;      // (8, 2048, 1024)

    float *scores;
    unsigned short *Wimg, *sentimg, *sentTimg;
    cudaGetSymbolAddress((void**)&scores,   g_scores);
    cudaGetSymbolAddress((void**)&Wimg,     g_Wimg);
    cudaGetSymbolAddress((void**)&sentimg,  g_sentimg);
    cudaGetSymbolAddress((void**)&sentTimg, g_sentTimg);

    cudaFuncSetAttribute(gemm3i,
                         cudaFuncAttributeMaxDynamicSharedMemorySize, DYN_SMEM);

    // 0) render B tile images (bandwidth-bound)
    {   // W: batch 1, rows=1024 (8 bands), K=1024 (32 chunks)
        int n2 = E_ * E_ / 2;
        build_img<<<(n2 + 255) / 256, 256>>>(W, Wimg, E_ * E_ / 2, E_ / 2,
                                             32, 8, n2);
    }
    {   // sent: batch 8, rows=512 (4 bands), K=1024 (32 chunks)
        int n2 = B_ * NS_ * E_ / 2;
        build_img<<<(n2 + 255) / 256, 256>>>(sent, sentimg, NS_ * E_ / 2,
                                             E_ / 2, 32, 4, n2);
    }
    build_imgT<<<dim3(E_ / 32, NS_ / 32, B_), dim3(32, 8)>>>(sent, sentTimg);

    // 1) w = word @ W^T -> combination[:, :1024]   (M=16384, N=1024, K=1024)
    gemm3i<<<dim3(E_ / BN, M_TOT / BM, 1), NTHREADS, DYN_SMEM>>>(
        word, Wimg, comb, nullptr,
        E_, 2 * E_, 0, E_,
        0, 0, 0, 0);

    // 2) scores[b] = w[b] @ sent[b]^T -> g_scores  (M=2048, N=512, K=1024)
    gemm3i<<<dim3(NS_ / BN, S_ / BM, B_), NTHREADS, DYN_SMEM>>>(
        comb, sentimg, scores, nullptr,
        2 * E_, NS_, 0, E_,
        (size_t)S_ * 2 * E_, (size_t)4 * 32 * BLK_H,
        (size_t)S_ * NS_, 0);

    // 3) softmax over 512 sentence scores per (b,s) row
    softmax_rows<<<M_TOT, 256>>>();

    // 4) g[b] = att[b] @ sent[b] -> comb[:, 1024:] AND g  (M=2048, N=1024, K=512)
    gemm3i<<<dim3(E_ / BN, S_ / BM, B_), NTHREADS, DYN_SMEM>>>(
        scores, sentTimg, comb + E_, gout,
        NS_, 2 * E_, E_, NS_,
        (size_t)S_ * NS_, (size_t)8 * 16 * BLK_H,
        (size_t)S_ * 2 * E_, (size_t)S_ * E_);
}